// round 1
// baseline (speedup 1.0000x reference)
#include <cuda_runtime.h>
#include <cuda_bf16.h>
#include <math.h>

#define BB 16384
#define LL 32

// scratch (no allocation allowed)
__device__ float g_z[BB * 8];
__device__ float g_T10[BB];

__device__ __forceinline__ float tanh_fast(float x) {
    float e = __expf(2.0f * x);
    return 1.0f - __fdividef(2.0f, e + 1.0f);
}

__device__ __forceinline__ float2 dxval(float s, float2 x0, float2 x1, float2 m0, float2 m1) {
    float s2 = s * s;
    float cx0 = 6.f * s2 - 6.f * s;
    float cm0 = 3.f * s2 - 4.f * s + 1.f;
    float cx1 = -6.f * s2 + 6.f * s;
    float cm1 = 3.f * s2 - 2.f * s;
    float2 r;
    r.x = cx0 * x0.x + cm0 * m0.x + cx1 * x1.x + cm1 * m1.x;
    r.y = cx0 * x0.y + cm0 * m0.y + cx1 * x1.y + cm1 * m1.y;
    return r;
}

// F(s,z) for one row, distributed over 4 lanes (g = lane&3).
__device__ __forceinline__ void Feval(const float* zz, float2 d,
                                      const float* sW1, const float* sW2T,
                                      const float* sB1, const float* sB2,
                                      int g, int xo0, int xo1, int xo2, int xo3,
                                      float* out) {
    float a[16];
#pragma unroll
    for (int j = 0; j < 16; j++) a[j] = 0.f;

#pragma unroll 4
    for (int kk = g; kk < 256; kk += 4) {
        const float4* w1 = reinterpret_cast<const float4*>(sW1 + kk * 8);
        float4 wA = w1[0];
        float4 wB = w1[1];
        float h = sB1[kk];
        h = fmaf(wA.x, zz[0], h);
        h = fmaf(wA.y, zz[1], h);
        h = fmaf(wA.z, zz[2], h);
        h = fmaf(wA.w, zz[3], h);
        h = fmaf(wB.x, zz[4], h);
        h = fmaf(wB.y, zz[5], h);
        h = fmaf(wB.z, zz[6], h);
        h = fmaf(wB.w, zz[7], h);
        h = fmaxf(h, 0.f);

        const float* base = sW2T + kk * 16;
        float4 c0 = *reinterpret_cast<const float4*>(base + xo0);
        float4 c1 = *reinterpret_cast<const float4*>(base + xo1);
        float4 c2 = *reinterpret_cast<const float4*>(base + xo2);
        float4 c3 = *reinterpret_cast<const float4*>(base + xo3);
        a[0]  = fmaf(c0.x, h, a[0]);
        a[1]  = fmaf(c0.y, h, a[1]);
        a[2]  = fmaf(c0.z, h, a[2]);
        a[3]  = fmaf(c0.w, h, a[3]);
        a[4]  = fmaf(c1.x, h, a[4]);
        a[5]  = fmaf(c1.y, h, a[5]);
        a[6]  = fmaf(c1.z, h, a[6]);
        a[7]  = fmaf(c1.w, h, a[7]);
        a[8]  = fmaf(c2.x, h, a[8]);
        a[9]  = fmaf(c2.y, h, a[9]);
        a[10] = fmaf(c2.z, h, a[10]);
        a[11] = fmaf(c2.w, h, a[11]);
        a[12] = fmaf(c3.x, h, a[12]);
        a[13] = fmaf(c3.y, h, a[13]);
        a[14] = fmaf(c3.z, h, a[14]);
        a[15] = fmaf(c3.w, h, a[15]);
    }
    // reduce across the 4 lanes of the group
#pragma unroll
    for (int j = 0; j < 16; j++) {
        a[j] += __shfl_xor_sync(0xffffffffu, a[j], 1);
        a[j] += __shfl_xor_sync(0xffffffffu, a[j], 2);
    }
#pragma unroll
    for (int hh = 0; hh < 8; hh++) {
        float gf = tanh_fast(a[2 * hh]     + sB2[2 * hh]);
        float gx = tanh_fast(a[2 * hh + 1] + sB2[2 * hh + 1]);
        out[hh] = gf * d.x + gx * d.y;
    }
}

__device__ __forceinline__ void substep(float* z, float2 xa, float2 xb, float2 m0, float2 m1,
                                        float s0,
                                        const float* sW1, const float* sW2T,
                                        const float* sB1, const float* sB2,
                                        int g, int xo0, int xo1, int xo2, int xo3) {
    float2 dA = dxval(s0,          xa, xb, m0, m1);
    float2 dB = dxval(s0 + 0.25f,  xa, xb, m0, m1);
    float2 dC = dxval(s0 + 0.5f,   xa, xb, m0, m1);

    float kcur[8], ksum[8], zt[8];
    Feval(z, dA, sW1, sW2T, sB1, sB2, g, xo0, xo1, xo2, xo3, kcur); // k1
#pragma unroll
    for (int j = 0; j < 8; j++) { ksum[j] = kcur[j]; zt[j] = fmaf(0.25f, kcur[j], z[j]); }
    Feval(zt, dB, sW1, sW2T, sB1, sB2, g, xo0, xo1, xo2, xo3, kcur); // k2
#pragma unroll
    for (int j = 0; j < 8; j++) { ksum[j] = fmaf(2.f, kcur[j], ksum[j]); zt[j] = fmaf(0.25f, kcur[j], z[j]); }
    Feval(zt, dB, sW1, sW2T, sB1, sB2, g, xo0, xo1, xo2, xo3, kcur); // k3
#pragma unroll
    for (int j = 0; j < 8; j++) { ksum[j] = fmaf(2.f, kcur[j], ksum[j]); zt[j] = fmaf(0.5f, kcur[j], z[j]); }
    Feval(zt, dC, sW1, sW2T, sB1, sB2, g, xo0, xo1, xo2, xo3, kcur); // k4
#pragma unroll
    for (int j = 0; j < 8; j++) z[j] = fmaf(1.f / 12.f, ksum[j] + kcur[j], z[j]);
}

__global__ void __launch_bounds__(128, 4)
k1_ode(const float* __restrict__ X_in, const float* __restrict__ fa_in,
       const int* __restrict__ fa_len,
       const float* __restrict__ W_init, const float* __restrict__ b_init,
       const float* __restrict__ W1, const float* __restrict__ b1,
       const float* __restrict__ W2, const float* __restrict__ b2) {
    __shared__ float sW1[256 * 8];
    __shared__ float sW2T[256 * 16];
    __shared__ float sB1[256];
    __shared__ float sB2[16];
    __shared__ float sWI[16];
    __shared__ float sBI[8];
    __shared__ float2 sX[32][32];

    int tid = threadIdx.x;
    for (int i = tid; i < 256 * 8; i += blockDim.x) sW1[i] = W1[i];
    // W2 is (16,256); store transposed [k][j] with XOR swizzle of the 4 float4-chunks
    for (int i = tid; i < 16 * 256; i += blockDim.x) {
        int j = i >> 8;       // 0..15
        int k = i & 255;      // 0..255
        int pc = (j >> 2) ^ (k & 3);
        sW2T[k * 16 + pc * 4 + (j & 3)] = W2[i];
    }
    for (int i = tid; i < 256; i += blockDim.x) sB1[i] = b1[i];
    if (tid < 16) sB2[tid] = b2[tid];
    if (tid < 16) sWI[tid] = W_init[tid];
    if (tid < 8)  sBI[tid] = b_init[tid];

    int lane = tid & 31;
    int g = lane & 3;
    int rl = lane >> 2;
    int rib = (tid >> 5) * 8 + rl;          // 0..31 row within block
    int row = blockIdx.x * 32 + rib;

    const float* Xr = X_in + row * LL;
    const float* Fr = fa_in + row * LL;
    int fl = fa_len[row];

    float s = 0.f;
    for (int t = g; t < LL; t += 4) s += Xr[t];
    s += __shfl_xor_sync(0xffffffffu, s, 1);
    s += __shfl_xor_sync(0xffffffffu, s, 2);
    float mean = s / (float)fl;

    int shift = LL - fl;
    int li = 2 * fl - LL - 1;
    float lastX = (li >= 0) ? (Xr[li] / mean) : 0.f;
    float lastF = Fr[fl - 1];

    for (int p = g; p < LL; p += 4) {
        float fa, xx;
        if (p < shift) { fa = lastF; xx = lastX; }
        else           { fa = Fr[p - shift]; xx = Xr[p - shift] / mean; }
        sX[rib][p] = make_float2(fa, xx);
    }
    __syncthreads();

    float2 x0 = sX[rib][0];
    float z[8];
#pragma unroll
    for (int j = 0; j < 8; j++)
        z[j] = sBI[j] + sWI[2 * j] * x0.x + sWI[2 * j + 1] * x0.y;

    int xo0 = (0 ^ g) * 4, xo1 = (1 ^ g) * 4, xo2 = (2 ^ g) * 4, xo3 = (3 ^ g) * 4;

    float2 xa = x0, m0 = make_float2(0.f, 0.f), m1;
    for (int i = 0; i < LL - 1; i++) {
        float2 xb = sX[rib][i + 1];
        m1.x = xb.x - xa.x;
        m1.y = xb.y - xa.y;
        if (i == 0) m0 = m1;
        substep(z, xa, xb, m0, m1, 0.0f, sW1, sW2T, sB1, sB2, g, xo0, xo1, xo2, xo3);
        substep(z, xa, xb, m0, m1, 0.5f, sW1, sW2T, sB1, sB2, g, xo0, xo1, xo2, xo3);
        m0 = m1;
        xa = xb;
    }
    // all 4 lanes hold identical z; each writes 2 components
    g_z[row * 8 + 2 * g]     = z[2 * g];
    g_z[row * 8 + 2 * g + 1] = z[2 * g + 1];
}

__global__ void __launch_bounds__(128)
k2_readout(const float* __restrict__ Wr1, const float* __restrict__ br1,
           const float* __restrict__ Wr2, const float* __restrict__ br2,
           const float* __restrict__ Wr3, const float* __restrict__ br3) {
    __shared__ __align__(16) float h1s[4][200];
    int lane = threadIdx.x & 31;
    int w = threadIdx.x >> 5;
    int row = blockIdx.x * 4 + w;

    float z[8];
#pragma unroll
    for (int j = 0; j < 8; j++) z[j] = g_z[row * 8 + j];

    for (int j = lane; j < 200; j += 32) {
        const float4* wr = reinterpret_cast<const float4*>(Wr1 + j * 8);
        float4 a = __ldg(wr), b = __ldg(wr + 1);
        float h = br1[j];
        h = fmaf(a.x, z[0], h); h = fmaf(a.y, z[1], h);
        h = fmaf(a.z, z[2], h); h = fmaf(a.w, z[3], h);
        h = fmaf(b.x, z[4], h); h = fmaf(b.y, z[5], h);
        h = fmaf(b.z, z[6], h); h = fmaf(b.w, z[7], h);
        h1s[w][j] = h * normcdff(h);   // exact gelu
    }
    __syncwarp();

    float part = 0.f;
    for (int j = lane; j < 200; j += 32) {
        const float4* wr = reinterpret_cast<const float4*>(Wr2 + j * 200);
        float acc = br2[j];
#pragma unroll 5
        for (int q = 0; q < 50; q++) {
            float4 ww = __ldg(wr + q);
            float4 hh = *reinterpret_cast<const float4*>(&h1s[w][q * 4]);
            acc = fmaf(ww.x, hh.x, acc);
            acc = fmaf(ww.y, hh.y, acc);
            acc = fmaf(ww.z, hh.z, acc);
            acc = fmaf(ww.w, hh.w, acc);
        }
        float h2 = acc * normcdff(acc);
        part = fmaf(Wr3[j], h2, part);
    }
#pragma unroll
    for (int m = 16; m >= 1; m >>= 1) part += __shfl_xor_sync(0xffffffffu, part, m);

    if (lane == 0) {
        float t = part + br3[0];
        float sg = 1.0f / (1.0f + expf(-t));
        g_T10[row] = 0.1f + sg * (7.0f - 0.1f);
    }
}

__global__ void __launch_bounds__(128)
k3_out(const float* __restrict__ fa_in, const float* __restrict__ TR,
       const int* __restrict__ fa_len, float* __restrict__ out) {
    int lane = threadIdx.x & 31;
    int w = threadIdx.x >> 5;
    int row = blockIdx.x * 4 + w;

    float T10 = g_T10[row];
    float R1 = 1.0f / T10;
    float E = expf(-TR[row] * R1);
    float fa = fa_in[row * LL + lane];
    float xo = (1.0f - E) * sinf(fa) / (1.0f - cosf(fa) * E);

    float ssum = xo;
#pragma unroll
    for (int m = 16; m >= 1; m >>= 1) ssum += __shfl_xor_sync(0xffffffffu, ssum, m);

    float fl = (float)fa_len[row];
    out[row * LL + lane] = xo * fl / ssum;
    if (lane == 0) {
        out[BB * LL + row] = T10;       // T10
        out[BB * LL + BB + row] = 1.0f; // M0
    }
}

extern "C" void kernel_launch(void* const* d_in, const int* in_sizes, int n_in,
                              void* d_out, int out_size) {
    const float* X_fa_in   = (const float*)d_in[0];
    const float* fa_vals_in= (const float*)d_in[1];
    const float* TR_vals   = (const float*)d_in[2];
    const float* W_init    = (const float*)d_in[3];
    const float* b_init    = (const float*)d_in[4];
    const float* W1        = (const float*)d_in[5];
    const float* b1        = (const float*)d_in[6];
    const float* W2        = (const float*)d_in[7];
    const float* b2        = (const float*)d_in[8];
    const float* Wr1       = (const float*)d_in[9];
    const float* br1       = (const float*)d_in[10];
    const float* Wr2       = (const float*)d_in[11];
    const float* br2       = (const float*)d_in[12];
    const float* Wr3       = (const float*)d_in[13];
    const float* br3       = (const float*)d_in[14];
    // d_in[15] = fa_mask (unused)
    const int*   fa_len    = (const int*)d_in[16];

    float* out = (float*)d_out;

    k1_ode<<<BB / 32, 128>>>(X_fa_in, fa_vals_in, fa_len, W_init, b_init, W1, b1, W2, b2);
    k2_readout<<<BB / 4, 128>>>(Wr1, br1, Wr2, br2, Wr3, br3);
    k3_out<<<BB / 4, 128>>>(fa_vals_in, TR_vals, fa_len, out);
}

// round 2
// speedup vs baseline: 1.5013x; 1.5013x over previous
#include <cuda_runtime.h>
#include <cuda_bf16.h>
#include <math.h>

#define BB 16384
#define LL 32

// scratch (no allocation allowed)
__device__ float g_z[BB * 8];
__device__ float g_T10[BB];

__device__ __forceinline__ float tanh_fast(float x) {
    float e = __expf(2.0f * x);
    return 1.0f - __fdividef(2.0f, e + 1.0f);
}

__device__ __forceinline__ float2 dxval(float s, float2 x0, float2 x1, float2 m0, float2 m1) {
    float s2 = s * s;
    float cx0 = 6.f * s2 - 6.f * s;
    float cm0 = 3.f * s2 - 4.f * s + 1.f;
    float cx1 = -6.f * s2 + 6.f * s;
    float cm1 = 3.f * s2 - 2.f * s;
    float2 r;
    r.x = cx0 * x0.x + cm0 * m0.x + cx1 * x1.x + cm1 * m1.x;
    r.y = cx0 * x0.y + cm0 * m0.y + cx1 * x1.y + cm1 * m1.y;
    return r;
}

// F(s,z) for one row. Two lanes per row (g = lane&1) split k; weight loads are
// warp-broadcast (all same-parity lanes read identical addresses).
__device__ __forceinline__ void Feval(const float* zz, float2 d,
                                      const float* sW1, const float* sW2T,
                                      const float* sB1, const float* sB2,
                                      int g, float* out) {
    float a[16];
#pragma unroll
    for (int j = 0; j < 16; j++) a[j] = 0.f;

#pragma unroll 4
    for (int kk = g; kk < 256; kk += 2) {
        const float4* w1 = reinterpret_cast<const float4*>(sW1 + kk * 8);
        float4 wA = w1[0];
        float4 wB = w1[1];
        float h = sB1[kk];
        h = fmaf(wA.x, zz[0], h);
        h = fmaf(wA.y, zz[1], h);
        h = fmaf(wA.z, zz[2], h);
        h = fmaf(wA.w, zz[3], h);
        h = fmaf(wB.x, zz[4], h);
        h = fmaf(wB.y, zz[5], h);
        h = fmaf(wB.z, zz[6], h);
        h = fmaf(wB.w, zz[7], h);
        h = fmaxf(h, 0.f);

        const float4* w2 = reinterpret_cast<const float4*>(sW2T + kk * 16);
        float4 c0 = w2[0];
        float4 c1 = w2[1];
        float4 c2 = w2[2];
        float4 c3 = w2[3];
        a[0]  = fmaf(c0.x, h, a[0]);
        a[1]  = fmaf(c0.y, h, a[1]);
        a[2]  = fmaf(c0.z, h, a[2]);
        a[3]  = fmaf(c0.w, h, a[3]);
        a[4]  = fmaf(c1.x, h, a[4]);
        a[5]  = fmaf(c1.y, h, a[5]);
        a[6]  = fmaf(c1.z, h, a[6]);
        a[7]  = fmaf(c1.w, h, a[7]);
        a[8]  = fmaf(c2.x, h, a[8]);
        a[9]  = fmaf(c2.y, h, a[9]);
        a[10] = fmaf(c2.z, h, a[10]);
        a[11] = fmaf(c2.w, h, a[11]);
        a[12] = fmaf(c3.x, h, a[12]);
        a[13] = fmaf(c3.y, h, a[13]);
        a[14] = fmaf(c3.z, h, a[14]);
        a[15] = fmaf(c3.w, h, a[15]);
    }
    // reduce across the lane pair
#pragma unroll
    for (int j = 0; j < 16; j++) a[j] += __shfl_xor_sync(0xffffffffu, a[j], 1);

#pragma unroll
    for (int hh = 0; hh < 8; hh++) {
        float gf = tanh_fast(a[2 * hh]     + sB2[2 * hh]);
        float gx = tanh_fast(a[2 * hh + 1] + sB2[2 * hh + 1]);
        out[hh] = gf * d.x + gx * d.y;
    }
}

__device__ __forceinline__ void substep(float* z, float2 xa, float2 xb, float2 m0, float2 m1,
                                        float s0,
                                        const float* sW1, const float* sW2T,
                                        const float* sB1, const float* sB2, int g) {
    float2 dA = dxval(s0,          xa, xb, m0, m1);
    float2 dB = dxval(s0 + 0.25f,  xa, xb, m0, m1);
    float2 dC = dxval(s0 + 0.5f,   xa, xb, m0, m1);

    float kcur[8], ksum[8], zt[8];
    Feval(z, dA, sW1, sW2T, sB1, sB2, g, kcur); // k1
#pragma unroll
    for (int j = 0; j < 8; j++) { ksum[j] = kcur[j]; zt[j] = fmaf(0.25f, kcur[j], z[j]); }
    Feval(zt, dB, sW1, sW2T, sB1, sB2, g, kcur); // k2
#pragma unroll
    for (int j = 0; j < 8; j++) { ksum[j] = fmaf(2.f, kcur[j], ksum[j]); zt[j] = fmaf(0.25f, kcur[j], z[j]); }
    Feval(zt, dB, sW1, sW2T, sB1, sB2, g, kcur); // k3
#pragma unroll
    for (int j = 0; j < 8; j++) { ksum[j] = fmaf(2.f, kcur[j], ksum[j]); zt[j] = fmaf(0.5f, kcur[j], z[j]); }
    Feval(zt, dC, sW1, sW2T, sB1, sB2, g, kcur); // k4
#pragma unroll
    for (int j = 0; j < 8; j++) z[j] = fmaf(1.f / 12.f, ksum[j] + kcur[j], z[j]);
}

__global__ void __launch_bounds__(64, 4)
k1_ode(const float* __restrict__ X_in, const float* __restrict__ fa_in,
       const int* __restrict__ fa_len,
       const float* __restrict__ W_init, const float* __restrict__ b_init,
       const float* __restrict__ W1, const float* __restrict__ b1,
       const float* __restrict__ W2, const float* __restrict__ b2) {
    __shared__ float sW1[256 * 8];
    __shared__ float sW2T[256 * 16];
    __shared__ float sB1[256];
    __shared__ float sB2[16];
    __shared__ float sWI[16];
    __shared__ float sBI[8];
    __shared__ float2 sX[32][33];   // padded: 16 rows/warp hit distinct banks

    int tid = threadIdx.x;   // 0..63
    for (int i = tid; i < 256 * 8; i += 64) sW1[i] = W1[i];
    // W2 is (16,256); store transposed [k][j]
    for (int i = tid; i < 16 * 256; i += 64) {
        int j = i >> 8;    // 0..15
        int k = i & 255;   // 0..255
        sW2T[k * 16 + j] = W2[i];
    }
    for (int i = tid; i < 256; i += 64) sB1[i] = b1[i];
    if (tid < 16) sB2[tid] = b2[tid];
    if (tid < 16) sWI[tid] = W_init[tid];
    if (tid < 8)  sBI[tid] = b_init[tid];

    int lane = tid & 31;
    int g = lane & 1;            // k-parity
    int r = lane >> 1;           // row within warp, 0..15
    int rib = (tid >> 5) * 16 + r;   // 0..31 row within block
    int row = blockIdx.x * 32 + rib;

    const float* Xr = X_in + row * LL;
    const float* Fr = fa_in + row * LL;
    int fl = fa_len[row];

    float s = 0.f;
    for (int t = g; t < LL; t += 2) s += Xr[t];
    s += __shfl_xor_sync(0xffffffffu, s, 1);
    float mean = s / (float)fl;

    int shift = LL - fl;
    int li = 2 * fl - LL - 1;
    float lastX = (li >= 0) ? (Xr[li] / mean) : 0.f;
    float lastF = Fr[fl - 1];

    for (int p = g; p < LL; p += 2) {
        float fa, xx;
        if (p < shift) { fa = lastF; xx = lastX; }
        else           { fa = Fr[p - shift]; xx = Xr[p - shift] / mean; }
        sX[rib][p] = make_float2(fa, xx);
    }
    __syncthreads();

    float2 x0 = sX[rib][0];
    float z[8];
#pragma unroll
    for (int j = 0; j < 8; j++)
        z[j] = sBI[j] + sWI[2 * j] * x0.x + sWI[2 * j + 1] * x0.y;

    float2 xa = x0, m0 = make_float2(0.f, 0.f), m1;
    for (int i = 0; i < LL - 1; i++) {
        float2 xb = sX[rib][i + 1];
        m1.x = xb.x - xa.x;
        m1.y = xb.y - xa.y;
        if (i == 0) m0 = m1;
        substep(z, xa, xb, m0, m1, 0.0f, sW1, sW2T, sB1, sB2, g);
        substep(z, xa, xb, m0, m1, 0.5f, sW1, sW2T, sB1, sB2, g);
        m0 = m1;
        xa = xb;
    }
    // both lanes hold identical z; each writes 4 components
#pragma unroll
    for (int j = 0; j < 4; j++)
        g_z[row * 8 + g * 4 + j] = z[g * 4 + j];
}

__global__ void __launch_bounds__(128)
k2_readout(const float* __restrict__ Wr1, const float* __restrict__ br1,
           const float* __restrict__ Wr2, const float* __restrict__ br2,
           const float* __restrict__ Wr3, const float* __restrict__ br3) {
    __shared__ __align__(16) float h1s[4][200];
    int lane = threadIdx.x & 31;
    int w = threadIdx.x >> 5;
    int row = blockIdx.x * 4 + w;

    float z[8];
#pragma unroll
    for (int j = 0; j < 8; j++) z[j] = g_z[row * 8 + j];

    for (int j = lane; j < 200; j += 32) {
        const float4* wr = reinterpret_cast<const float4*>(Wr1 + j * 8);
        float4 a = __ldg(wr), b = __ldg(wr + 1);
        float h = br1[j];
        h = fmaf(a.x, z[0], h); h = fmaf(a.y, z[1], h);
        h = fmaf(a.z, z[2], h); h = fmaf(a.w, z[3], h);
        h = fmaf(b.x, z[4], h); h = fmaf(b.y, z[5], h);
        h = fmaf(b.z, z[6], h); h = fmaf(b.w, z[7], h);
        h1s[w][j] = h * normcdff(h);   // exact gelu
    }
    __syncwarp();

    float part = 0.f;
    for (int j = lane; j < 200; j += 32) {
        const float4* wr = reinterpret_cast<const float4*>(Wr2 + j * 200);
        float acc = br2[j];
#pragma unroll 5
        for (int q = 0; q < 50; q++) {
            float4 ww = __ldg(wr + q);
            float4 hh = *reinterpret_cast<const float4*>(&h1s[w][q * 4]);
            acc = fmaf(ww.x, hh.x, acc);
            acc = fmaf(ww.y, hh.y, acc);
            acc = fmaf(ww.z, hh.z, acc);
            acc = fmaf(ww.w, hh.w, acc);
        }
        float h2 = acc * normcdff(acc);
        part = fmaf(Wr3[j], h2, part);
    }
#pragma unroll
    for (int m = 16; m >= 1; m >>= 1) part += __shfl_xor_sync(0xffffffffu, part, m);

    if (lane == 0) {
        float t = part + br3[0];
        float sg = 1.0f / (1.0f + expf(-t));
        g_T10[row] = 0.1f + sg * (7.0f - 0.1f);
    }
}

__global__ void __launch_bounds__(128)
k3_out(const float* __restrict__ fa_in, const float* __restrict__ TR,
       const int* __restrict__ fa_len, float* __restrict__ out) {
    int lane = threadIdx.x & 31;
    int w = threadIdx.x >> 5;
    int row = blockIdx.x * 4 + w;

    float T10 = g_T10[row];
    float R1 = 1.0f / T10;
    float E = expf(-TR[row] * R1);
    float fa = fa_in[row * LL + lane];
    float xo = (1.0f - E) * sinf(fa) / (1.0f - cosf(fa) * E);

    float ssum = xo;
#pragma unroll
    for (int m = 16; m >= 1; m >>= 1) ssum += __shfl_xor_sync(0xffffffffu, ssum, m);

    float fl = (float)fa_len[row];
    out[row * LL + lane] = xo * fl / ssum;
    if (lane == 0) {
        out[BB * LL + row] = T10;       // T10
        out[BB * LL + BB + row] = 1.0f; // M0
    }
}

extern "C" void kernel_launch(void* const* d_in, const int* in_sizes, int n_in,
                              void* d_out, int out_size) {
    const float* X_fa_in    = (const float*)d_in[0];
    const float* fa_vals_in = (const float*)d_in[1];
    const float* TR_vals    = (const float*)d_in[2];
    const float* W_init     = (const float*)d_in[3];
    const float* b_init     = (const float*)d_in[4];
    const float* W1         = (const float*)d_in[5];
    const float* b1         = (const float*)d_in[6];
    const float* W2         = (const float*)d_in[7];
    const float* b2         = (const float*)d_in[8];
    const float* Wr1        = (const float*)d_in[9];
    const float* br1        = (const float*)d_in[10];
    const float* Wr2        = (const float*)d_in[11];
    const float* br2        = (const float*)d_in[12];
    const float* Wr3        = (const float*)d_in[13];
    const float* br3        = (const float*)d_in[14];
    // d_in[15] = fa_mask (unused)
    const int*   fa_len     = (const int*)d_in[16];

    float* out = (float*)d_out;

    k1_ode<<<BB / 32, 64>>>(X_fa_in, fa_vals_in, fa_len, W_init, b_init, W1, b1, W2, b2);
    k2_readout<<<BB / 4, 128>>>(Wr1, br1, Wr2, br2, Wr3, br3);
    k3_out<<<BB / 4, 128>>>(fa_vals_in, TR_vals, fa_len, out);
}

// round 3
// speedup vs baseline: 1.8910x; 1.2596x over previous
#include <cuda_runtime.h>
#include <cuda_bf16.h>
#include <math.h>

#define BB 16384
#define LL 32

typedef unsigned long long ull;

// scratch (no allocation allowed)
__device__ float g_z[BB * 8];
__device__ float g_T10[BB];

__device__ __forceinline__ ull pack2(float lo, float hi) {
    ull r; asm("mov.b64 %0,{%1,%2};" : "=l"(r) : "f"(lo), "f"(hi)); return r;
}
__device__ __forceinline__ void unpack2(ull v, float& lo, float& hi) {
    asm("mov.b64 {%0,%1},%2;" : "=f"(lo), "=f"(hi) : "l"(v));
}
__device__ __forceinline__ ull fma2(ull a, ull b, ull c) {
    ull d; asm("fma.rn.f32x2 %0,%1,%2,%3;" : "=l"(d) : "l"(a), "l"(b), "l"(c)); return d;
}
__device__ __forceinline__ ull add2(ull a, ull b) {
    ull d; asm("add.rn.f32x2 %0,%1,%2;" : "=l"(d) : "l"(a), "l"(b)); return d;
}

__device__ __forceinline__ float tanh_fast(float x) {
    float e = __expf(2.0f * x);
    return 1.0f - __fdividef(2.0f, e + 1.0f);
}

__device__ __forceinline__ float2 dxval(float s, float2 x0, float2 x1, float2 m0, float2 m1) {
    float s2 = s * s;
    float cx0 = 6.f * s2 - 6.f * s;
    float cm0 = 3.f * s2 - 4.f * s + 1.f;
    float cx1 = -6.f * s2 + 6.f * s;
    float cm1 = 3.f * s2 - 2.f * s;
    float2 r;
    r.x = cx0 * x0.x + cm0 * m0.x + cx1 * x1.x + cm1 * m1.x;
    r.y = cx0 * x0.y + cm0 * m0.y + cx1 * x1.y + cm1 * m1.y;
    return r;
}

// F(s,z) for one row. Two lanes per row (g = lane&1) split k; weight loads are
// warp-broadcast. All state packed f32x2.
__device__ __forceinline__ void Feval(const ull* zp, float2 d,
                                      const float* sW1, const float* sW2T,
                                      const ull* sB1p, const float* sB2,
                                      int g, ull* kout) {
    ull a2[8];
#pragma unroll
    for (int j = 0; j < 8; j++) a2[j] = 0ull;

#pragma unroll 4
    for (int kk = g; kk < 256; kk += 2) {
        ulonglong2 w1a = *reinterpret_cast<const ulonglong2*>(sW1 + kk * 8);
        ulonglong2 w1b = *reinterpret_cast<const ulonglong2*>(sW1 + kk * 8 + 4);
        ull acc = fma2(w1a.x, zp[0], sB1p[kk]);
        acc = fma2(w1a.y, zp[1], acc);
        acc = fma2(w1b.x, zp[2], acc);
        acc = fma2(w1b.y, zp[3], acc);
        float alo, ahi; unpack2(acc, alo, ahi);
        float h = fmaxf(alo + ahi, 0.f);
        ull hh = pack2(h, h);

        ulonglong2 c0 = *reinterpret_cast<const ulonglong2*>(sW2T + kk * 16);
        ulonglong2 c1 = *reinterpret_cast<const ulonglong2*>(sW2T + kk * 16 + 4);
        ulonglong2 c2 = *reinterpret_cast<const ulonglong2*>(sW2T + kk * 16 + 8);
        ulonglong2 c3 = *reinterpret_cast<const ulonglong2*>(sW2T + kk * 16 + 12);
        a2[0] = fma2(c0.x, hh, a2[0]);
        a2[1] = fma2(c0.y, hh, a2[1]);
        a2[2] = fma2(c1.x, hh, a2[2]);
        a2[3] = fma2(c1.y, hh, a2[3]);
        a2[4] = fma2(c2.x, hh, a2[4]);
        a2[5] = fma2(c2.y, hh, a2[5]);
        a2[6] = fma2(c3.x, hh, a2[6]);
        a2[7] = fma2(c3.y, hh, a2[7]);
    }
    float av[16];
#pragma unroll
    for (int j = 0; j < 8; j++) unpack2(a2[j], av[2 * j], av[2 * j + 1]);
    // reduce across the lane pair
#pragma unroll
    for (int j = 0; j < 16; j++) av[j] += __shfl_xor_sync(0xffffffffu, av[j], 1);

#pragma unroll
    for (int hh = 0; hh < 4; hh++) {
        float g0 = tanh_fast(av[4 * hh]     + sB2[4 * hh]);
        float g1 = tanh_fast(av[4 * hh + 1] + sB2[4 * hh + 1]);
        float g2 = tanh_fast(av[4 * hh + 2] + sB2[4 * hh + 2]);
        float g3 = tanh_fast(av[4 * hh + 3] + sB2[4 * hh + 3]);
        float o0 = g0 * d.x + g1 * d.y;
        float o1 = g2 * d.x + g3 * d.y;
        kout[hh] = pack2(o0, o1);
    }
}

__device__ __forceinline__ void substep(ull* z, float2 xa, float2 xb, float2 m0, float2 m1,
                                        float s0,
                                        const float* sW1, const float* sW2T,
                                        const ull* sB1p, const float* sB2, int g) {
    float2 dA = dxval(s0,          xa, xb, m0, m1);
    float2 dB = dxval(s0 + 0.25f,  xa, xb, m0, m1);
    float2 dC = dxval(s0 + 0.5f,   xa, xb, m0, m1);

    const ull C025 = pack2(0.25f, 0.25f);
    const ull C05  = pack2(0.5f, 0.5f);
    const ull C2   = pack2(2.f, 2.f);
    const ull C112 = pack2(1.f / 12.f, 1.f / 12.f);

    ull kc[4], ks[4], zt[4];
    Feval(z, dA, sW1, sW2T, sB1p, sB2, g, kc); // k1
#pragma unroll
    for (int j = 0; j < 4; j++) { ks[j] = kc[j]; zt[j] = fma2(C025, kc[j], z[j]); }
    Feval(zt, dB, sW1, sW2T, sB1p, sB2, g, kc); // k2
#pragma unroll
    for (int j = 0; j < 4; j++) { ks[j] = fma2(C2, kc[j], ks[j]); zt[j] = fma2(C025, kc[j], z[j]); }
    Feval(zt, dB, sW1, sW2T, sB1p, sB2, g, kc); // k3
#pragma unroll
    for (int j = 0; j < 4; j++) { ks[j] = fma2(C2, kc[j], ks[j]); zt[j] = fma2(C05, kc[j], z[j]); }
    Feval(zt, dC, sW1, sW2T, sB1p, sB2, g, kc); // k4
#pragma unroll
    for (int j = 0; j < 4; j++) z[j] = fma2(C112, add2(ks[j], kc[j]), z[j]);
}

__global__ void __launch_bounds__(32, 8)
k1_ode(const float* __restrict__ X_in, const float* __restrict__ fa_in,
       const int* __restrict__ fa_len,
       const float* __restrict__ W_init, const float* __restrict__ b_init,
       const float* __restrict__ W1, const float* __restrict__ b1,
       const float* __restrict__ W2, const float* __restrict__ b2) {
    __shared__ __align__(16) float sW1[256 * 8];
    __shared__ __align__(16) float sW2T[256 * 16];
    __shared__ __align__(16) ull   sB1p[256];   // (b1, 0) packed
    __shared__ float sB2[16];
    __shared__ float sWI[16];
    __shared__ float sBI[8];
    __shared__ float2 sX[16][33];

    int tid = threadIdx.x;   // 0..31
    for (int i = tid; i < 256 * 8; i += 32) sW1[i] = W1[i];
    // W2 is (16,256); store transposed [k][j]
    for (int i = tid; i < 16 * 256; i += 32) {
        int j = i >> 8;    // 0..15
        int k = i & 255;   // 0..255
        sW2T[k * 16 + j] = W2[i];
    }
    for (int i = tid; i < 256; i += 32) sB1p[i] = pack2(b1[i], 0.f);
    if (tid < 16) sB2[tid] = b2[tid];
    if (tid < 16) sWI[tid] = W_init[tid];
    if (tid < 8)  sBI[tid] = b_init[tid];

    int g = tid & 1;             // k-parity
    int r = tid >> 1;            // row within warp, 0..15
    int row = blockIdx.x * 16 + r;

    const float* Xr = X_in + row * LL;
    const float* Fr = fa_in + row * LL;
    int fl = fa_len[row];

    float s = 0.f;
    for (int t = g; t < LL; t += 2) s += Xr[t];
    s += __shfl_xor_sync(0xffffffffu, s, 1);
    float mean = s / (float)fl;

    int shift = LL - fl;
    int li = 2 * fl - LL - 1;
    float lastX = (li >= 0) ? (Xr[li] / mean) : 0.f;
    float lastF = Fr[fl - 1];

    for (int p = g; p < LL; p += 2) {
        float fa, xx;
        if (p < shift) { fa = lastF; xx = lastX; }
        else           { fa = Fr[p - shift]; xx = Xr[p - shift] / mean; }
        sX[r][p] = make_float2(fa, xx);
    }
    __syncwarp();

    float2 x0 = sX[r][0];
    ull z[4];
#pragma unroll
    for (int j = 0; j < 4; j++) {
        float z0 = sBI[2 * j]     + sWI[4 * j]     * x0.x + sWI[4 * j + 1] * x0.y;
        float z1 = sBI[2 * j + 1] + sWI[4 * j + 2] * x0.x + sWI[4 * j + 3] * x0.y;
        z[j] = pack2(z0, z1);
    }

    float2 xa = x0, m0 = make_float2(0.f, 0.f), m1;
    for (int i = 0; i < LL - 1; i++) {
        float2 xb = sX[r][i + 1];
        m1.x = xb.x - xa.x;
        m1.y = xb.y - xa.y;
        if (i == 0) m0 = m1;
        substep(z, xa, xb, m0, m1, 0.0f, sW1, sW2T, sB1p, sB2, g);
        substep(z, xa, xb, m0, m1, 0.5f, sW1, sW2T, sB1p, sB2, g);
        m0 = m1;
        xa = xb;
    }
    // both lanes hold identical z; each writes 2 packed components
#pragma unroll
    for (int j = 0; j < 2; j++) {
        float z0, z1; unpack2(z[g * 2 + j], z0, z1);
        g_z[row * 8 + g * 4 + 2 * j]     = z0;
        g_z[row * 8 + g * 4 + 2 * j + 1] = z1;
    }
}

__global__ void __launch_bounds__(128)
k2_readout(const float* __restrict__ Wr1, const float* __restrict__ br1,
           const float* __restrict__ Wr2, const float* __restrict__ br2,
           const float* __restrict__ Wr3, const float* __restrict__ br3) {
    __shared__ __align__(16) float h1s[4][200];
    int lane = threadIdx.x & 31;
    int w = threadIdx.x >> 5;
    int row = blockIdx.x * 4 + w;

    float z[8];
#pragma unroll
    for (int j = 0; j < 8; j++) z[j] = g_z[row * 8 + j];

    for (int j = lane; j < 200; j += 32) {
        const float4* wr = reinterpret_cast<const float4*>(Wr1 + j * 8);
        float4 a = __ldg(wr), b = __ldg(wr + 1);
        float h = br1[j];
        h = fmaf(a.x, z[0], h); h = fmaf(a.y, z[1], h);
        h = fmaf(a.z, z[2], h); h = fmaf(a.w, z[3], h);
        h = fmaf(b.x, z[4], h); h = fmaf(b.y, z[5], h);
        h = fmaf(b.z, z[6], h); h = fmaf(b.w, z[7], h);
        h1s[w][j] = h * normcdff(h);   // exact gelu
    }
    __syncwarp();

    float part = 0.f;
    for (int j = lane; j < 200; j += 32) {
        const float4* wr = reinterpret_cast<const float4*>(Wr2 + j * 200);
        float acc = br2[j];
#pragma unroll 5
        for (int q = 0; q < 50; q++) {
            float4 ww = __ldg(wr + q);
            float4 hh = *reinterpret_cast<const float4*>(&h1s[w][q * 4]);
            acc = fmaf(ww.x, hh.x, acc);
            acc = fmaf(ww.y, hh.y, acc);
            acc = fmaf(ww.z, hh.z, acc);
            acc = fmaf(ww.w, hh.w, acc);
        }
        float h2 = acc * normcdff(acc);
        part = fmaf(Wr3[j], h2, part);
    }
#pragma unroll
    for (int m = 16; m >= 1; m >>= 1) part += __shfl_xor_sync(0xffffffffu, part, m);

    if (lane == 0) {
        float t = part + br3[0];
        float sg = 1.0f / (1.0f + expf(-t));
        g_T10[row] = 0.1f + sg * (7.0f - 0.1f);
    }
}

__global__ void __launch_bounds__(128)
k3_out(const float* __restrict__ fa_in, const float* __restrict__ TR,
       const int* __restrict__ fa_len, float* __restrict__ out) {
    int lane = threadIdx.x & 31;
    int w = threadIdx.x >> 5;
    int row = blockIdx.x * 4 + w;

    float T10 = g_T10[row];
    float R1 = 1.0f / T10;
    float E = expf(-TR[row] * R1);
    float fa = fa_in[row * LL + lane];
    float xo = (1.0f - E) * sinf(fa) / (1.0f - cosf(fa) * E);

    float ssum = xo;
#pragma unroll
    for (int m = 16; m >= 1; m >>= 1) ssum += __shfl_xor_sync(0xffffffffu, ssum, m);

    float fl = (float)fa_len[row];
    out[row * LL + lane] = xo * fl / ssum;
    if (lane == 0) {
        out[BB * LL + row] = T10;       // T10
        out[BB * LL + BB + row] = 1.0f; // M0
    }
}

extern "C" void kernel_launch(void* const* d_in, const int* in_sizes, int n_in,
                              void* d_out, int out_size) {
    const float* X_fa_in    = (const float*)d_in[0];
    const float* fa_vals_in = (const float*)d_in[1];
    const float* TR_vals    = (const float*)d_in[2];
    const float* W_init     = (const float*)d_in[3];
    const float* b_init     = (const float*)d_in[4];
    const float* W1         = (const float*)d_in[5];
    const float* b1         = (const float*)d_in[6];
    const float* W2         = (const float*)d_in[7];
    const float* b2         = (const float*)d_in[8];
    const float* Wr1        = (const float*)d_in[9];
    const float* br1        = (const float*)d_in[10];
    const float* Wr2        = (const float*)d_in[11];
    const float* br2        = (const float*)d_in[12];
    const float* Wr3        = (const float*)d_in[13];
    const float* br3        = (const float*)d_in[14];
    // d_in[15] = fa_mask (unused)
    const int*   fa_len     = (const int*)d_in[16];

    float* out = (float*)d_out;

    k1_ode<<<BB / 16, 32>>>(X_fa_in, fa_vals_in, fa_len, W_init, b_init, W1, b1, W2, b2);
    k2_readout<<<BB / 4, 128>>>(Wr1, br1, Wr2, br2, Wr3, br3);
    k3_out<<<BB / 4, 128>>>(fa_vals_in, TR_vals, fa_len, out);
}